// round 15
// baseline (speedup 1.0000x reference)
#include <cuda_runtime.h>
#include <cuda_fp16.h>
#include <cstdint>
#include <math.h>

#define MATN 4096
#define NSQL ((size_t)MATN * (size_t)MATN)
#define TH2 2.25e-6f   // (1.5e-3)^2 max-row-norm^2 threshold

// ---------------- static device scratch ----------------
__device__ float g_X0[MATN * MATN];
__device__ float g_X1[MATN * MATN];
__device__ float g_S [MATN * MATN];
__device__ float g_P [MATN * MATN];
__device__ __half g_hA [MATN * MATN];
__device__ __half g_lA [MATN * MATN];
__device__ __half g_hAT[MATN * MATN];
__device__ __half g_hS [MATN * MATN];
__device__ __half g_lS [MATN * MATN];
__device__ __half g_hP [MATN * MATN];
__device__ __half g_lP [MATN * MATN];
__device__ float g_v[MATN];
__device__ float g_y[MATN];
__device__ float g_part[256];
__device__ float g_scal[4];    // [1]=sigma_ray^2  [2]=tmp norm
__device__ float g_rmax[2];    // max row-residual^2 (det 1, det 2)
__device__ int   g_f[2];       // rescue flags

// ---------------- helpers ----------------
__device__ __forceinline__ uint32_t smem_u32(const void* p) {
    uint32_t a;
    asm("{ .reg .u64 t; cvta.to.shared.u64 t, %1; cvt.u32.u64 %0, t; }" : "=r"(a) : "l"(p));
    return a;
}
__device__ __forceinline__ void cp16(uint32_t dst, const void* src) {
    asm volatile("cp.async.cg.shared.global [%0], [%1], 16;" :: "r"(dst), "l"(src));
}
#define CP_COMMIT() asm volatile("cp.async.commit_group;" ::: "memory")
#define CP_WAIT(N)  asm volatile("cp.async.wait_group %0;" :: "n"(N) : "memory")

#define LDSM_X4(r, a)                                                           \
    asm volatile("ldmatrix.sync.aligned.m8n8.x4.shared.b16 {%0,%1,%2,%3}, [%4];" \
        : "=r"((r)[0]), "=r"((r)[1]), "=r"((r)[2]), "=r"((r)[3]) : "r"(a))

__device__ __forceinline__ void mma_f16(float* d, const uint32_t* a,
                                        uint32_t b0, uint32_t b1) {
    asm volatile(
        "mma.sync.aligned.m16n8k16.row.col.f32.f16.f16.f32 "
        "{%0,%1,%2,%3}, {%4,%5,%6,%7}, {%8,%9}, {%0,%1,%2,%3};"
        : "+f"(d[0]), "+f"(d[1]), "+f"(d[2]), "+f"(d[3])
        : "r"(a[0]), "r"(a[1]), "r"(a[2]), "r"(a[3]), "r"(b0), "r"(b1));
}

// ---------------- fp16 tensor-core GEMM (mma.sync) ----------------
// C = sum_s A_s * B_s^T ; POLY=1: C = c2*D + c1*E + c0*I.
// TRI=1: only tiles with col-tile >= row-tile.  gate: skip kernel if *gate==0.
#define BROW 80
#define ABYTES (128 * BROW)
#define BUFBYTES (2 * ABYTES)

template<int POLY, int TRI>
__global__ void __launch_bounds__(256, 2)
mma_gemm(const __half* __restrict__ A0, const __half* __restrict__ B0,
         const __half* __restrict__ A1, const __half* __restrict__ B1,
         const __half* __restrict__ A2, const __half* __restrict__ B2,
         int nseg, float* __restrict__ C, const float* __restrict__ E,
         float c0, float c1, float c2,
         __half* __restrict__ Hi, __half* __restrict__ Lo,
         const int* __restrict__ gate)
{
    if (gate && *gate == 0) return;
    if (TRI && (int)blockIdx.x < (int)blockIdx.y) return;
    __shared__ __align__(16) char smem[2 * BUFBYTES];
    const uint32_t sbase = smem_u32(smem);

    const int tid  = threadIdx.x;
    const int wid  = tid >> 5, lane = tid & 31;
    const int wr   = wid & 3;
    const int wc   = wid >> 2;
    const int row0 = blockIdx.y * 128;
    const int col0 = blockIdx.x * 128;

    const __half* Aseg[3] = {A0, A1, A2};
    const __half* Bseg[3] = {B0, B1, B2};

    float acc[2][8][4];
    #pragma unroll
    for (int i = 0; i < 2; ++i)
        #pragma unroll
        for (int j = 0; j < 8; ++j)
            #pragma unroll
            for (int k = 0; k < 4; ++k) acc[i][j][k] = 0.f;

    auto load_chunk = [&](int ch, int buf) {
        const int seg = ch >> 7, kc = ch & 127;
        const __half* Ap = Aseg[seg] + (size_t)row0 * MATN + kc * 32;
        const __half* Bp = Bseg[seg] + (size_t)col0 * MATN + kc * 32;
        const uint32_t sa = sbase + buf * BUFBYTES;
        const uint32_t sb = sa + ABYTES;
        #pragma unroll
        for (int p = 0; p < 2; ++p) {
            int q = tid + p * 256;
            int r = q >> 2, s = q & 3;
            cp16(sa + r * BROW + s * 16, Ap + (size_t)r * MATN + s * 8);
            cp16(sb + r * BROW + s * 16, Bp + (size_t)r * MATN + s * 8);
        }
        CP_COMMIT();
    };

    const int total = nseg * 128;
    load_chunk(0, 0);

    for (int ch = 0; ch < total; ++ch) {
        const int buf = ch & 1;
        if (ch + 1 < total) { load_chunk(ch + 1, buf ^ 1); CP_WAIT(1); }
        else                { CP_WAIT(0); }
        __syncthreads();

        const uint32_t sa = sbase + buf * BUFBYTES;
        const uint32_t sb = sa + ABYTES;
        #pragma unroll
        for (int kk = 0; kk < 2; ++kk) {
            uint32_t af[2][4], bf[4][4];
            #pragma unroll
            for (int mt = 0; mt < 2; ++mt) {
                uint32_t addr = sa + (uint32_t)(wr * 32 + mt * 16 + (lane & 15)) * BROW
                              + kk * 32 + (lane >> 4) * 16;
                LDSM_X4(af[mt], addr);
            }
            #pragma unroll
            for (int bp = 0; bp < 4; ++bp) {
                int grp = lane >> 3, wi = lane & 7;
                uint32_t addr = sb + (uint32_t)(wc * 64 + bp * 16 + wi + (grp >> 1) * 8) * BROW
                              + kk * 32 + (grp & 1) * 16;
                LDSM_X4(bf[bp], addr);
            }
            #pragma unroll
            for (int mt = 0; mt < 2; ++mt)
                #pragma unroll
                for (int nt = 0; nt < 8; ++nt)
                    mma_f16(acc[mt][nt], af[mt], bf[nt >> 1][(nt & 1) * 2],
                            bf[nt >> 1][(nt & 1) * 2 + 1]);
        }
        __syncthreads();
    }

    #pragma unroll
    for (int mt = 0; mt < 2; ++mt) {
        #pragma unroll
        for (int half = 0; half < 2; ++half) {
            const int rg = row0 + wr * 32 + mt * 16 + (lane >> 2) + half * 8;
            const size_t rowbase = (size_t)rg * MATN;
            #pragma unroll
            for (int nt = 0; nt < 8; ++nt) {
                const int cc = col0 + wc * 64 + nt * 8 + (lane & 3) * 2;
                float v0 = acc[mt][nt][half * 2 + 0];
                float v1 = acc[mt][nt][half * 2 + 1];
                if (POLY) {
                    float2 e = *reinterpret_cast<const float2*>(E + rowbase + cc);
                    v0 = c2 * v0 + c1 * e.x + ((rg == cc)     ? c0 : 0.f);
                    v1 = c2 * v1 + c1 * e.y + ((rg == cc + 1) ? c0 : 0.f);
                }
                float2 o = make_float2(v0, v1);
                *reinterpret_cast<float2*>(C + rowbase + cc) = o;
                if (Hi) {
                    __half2 hh = __floats2half2_rn(v0, v1);
                    *reinterpret_cast<__half2*>(Hi + rowbase + cc) = hh;
                    if (Lo) {
                        float l0 = v0 - __half2float(__low2half(hh));
                        float l1 = v1 - __half2float(__high2half(hh));
                        *reinterpret_cast<__half2*>(Lo + rowbase + cc) =
                            __floats2half2_rn(l0, l1);
                    }
                }
            }
        }
    }
}

// ---------------- small kernels ----------------
__global__ void k_rst() { g_f[0] = 0; g_f[1] = 0; g_rmax[0] = 0.f; g_rmax[1] = 0.f; }

__global__ void k_sumsq(const float* __restrict__ x, int n, float* __restrict__ part) {
    __shared__ float sm[256];
    float acc = 0.f;
    for (int i = blockIdx.x * blockDim.x + threadIdx.x; i < n; i += gridDim.x * blockDim.x) {
        float v = x[i]; acc = fmaf(v, v, acc);
    }
    sm[threadIdx.x] = acc; __syncthreads();
    for (int s = 128; s > 0; s >>= 1) {
        if (threadIdx.x < s) sm[threadIdx.x] += sm[threadIdx.x + s];
        __syncthreads();
    }
    if (threadIdx.x == 0) part[blockIdx.x] = sm[0];
}
__global__ void k_finish(const float* __restrict__ part, float* __restrict__ dst) {
    __shared__ float sm[256];
    sm[threadIdx.x] = part[threadIdx.x]; __syncthreads();
    for (int s = 128; s > 0; s >>= 1) {
        if (threadIdx.x < s) sm[threadIdx.x] += sm[threadIdx.x + s];
        __syncthreads();
    }
    if (threadIdx.x == 0) *dst = sm[0];
}
__global__ void k_initv(float* v) {
    int j = blockIdx.x * blockDim.x + threadIdx.x;
    if (j < MATN) {
        unsigned h = (unsigned)j * 2654435761u;
        h ^= h >> 13; h *= 0x5bd1e995u; h ^= h >> 15;
        v[j] = ((float)(h & 0xFFFFu) / 65536.0f) - 0.5f + 0.001f;
    }
}
__global__ void k_normalize(float* v, const float* n2) {
    int j = blockIdx.x * blockDim.x + threadIdx.x;
    float s = rsqrtf(*n2 + 1e-30f);
    if (j < MATN) v[j] *= s;
}
__global__ void k_mvn(const float* __restrict__ H, const float* __restrict__ v,
                      float* __restrict__ y) {
    __shared__ float sm[128];
    int r = blockIdx.x;
    const float* row = H + (size_t)r * MATN;
    float acc = 0.f;
    for (int j = threadIdx.x; j < MATN; j += 128) acc = fmaf(row[j], v[j], acc);
    sm[threadIdx.x] = acc; __syncthreads();
    for (int s = 64; s > 0; s >>= 1) {
        if (threadIdx.x < s) sm[threadIdx.x] += sm[threadIdx.x + s];
        __syncthreads();
    }
    if (threadIdx.x == 0) y[r] = sm[0];
}
__global__ void k_mvt(const float* __restrict__ H, const float* __restrict__ y,
                      float* __restrict__ z) {
    __shared__ float sm[256];
    int tj = threadIdx.x & 31, gi = threadIdx.x >> 5;
    int j = blockIdx.x * 32 + tj;
    float acc = 0.f;
    for (int i = gi * 512; i < gi * 512 + 512; ++i)
        acc = fmaf(H[(size_t)i * MATN + j], y[i], acc);
    sm[threadIdx.x] = acc; __syncthreads();
    if (threadIdx.x < 32) {
        float t = 0.f;
        #pragma unroll
        for (int g = 0; g < 8; ++g) t += sm[threadIdx.x + 32 * g];
        z[j] = t;
    }
}

// split X -> (hi, lo) and transposed hi copy; optional prescale; gated.
__global__ void k_splitT(const float* __restrict__ X,
                         __half* __restrict__ hi, __half* __restrict__ lo,
                         __half* __restrict__ hiT,
                         int prescale, const int* __restrict__ gate) {
    if (gate && *gate == 0) return;
    __shared__ float t[32][33];
    float s = prescale ? (rsqrtf(g_scal[1] + 1e-30f) / 1.10f) : 1.0f;
    int x0 = blockIdx.x * 32, y0 = blockIdx.y * 32;
    #pragma unroll
    for (int j = 0; j < 32; j += 8) {
        int r = y0 + threadIdx.y + j, c = x0 + threadIdx.x;
        float v = X[(size_t)r * MATN + c] * s;
        t[threadIdx.y + j][threadIdx.x] = v;
        __half h = __float2half(v);
        hi[(size_t)r * MATN + c] = h;
        lo[(size_t)r * MATN + c] = __float2half(v - __half2float(h));
    }
    __syncthreads();
    #pragma unroll
    for (int j = 0; j < 32; j += 8) {
        int r = x0 + threadIdx.y + j, c = y0 + threadIdx.x;
        hiT[(size_t)r * MATN + c] = __float2half(t[threadIdx.x][threadIdx.y + j]);
    }
}

// mirror upper->lower (strictly below diagonal): hi always, lo if wlo; gated.
__global__ void k_mirror(const float* __restrict__ M,
                         __half* __restrict__ hi, __half* __restrict__ lo, int wlo,
                         const int* __restrict__ gate) {
    if (gate && *gate == 0) return;
    __shared__ float ta[32][33];
    int bi = blockIdx.y, bj = blockIdx.x;
    if (bj <= bi) return;
    int i0 = bi * 32, j0 = bj * 32;
    #pragma unroll
    for (int j = 0; j < 32; j += 8)
        ta[threadIdx.y + j][threadIdx.x] =
            M[(size_t)(i0 + threadIdx.y + j) * MATN + j0 + threadIdx.x];
    __syncthreads();
    #pragma unroll
    for (int j = 0; j < 32; j += 8) {
        size_t idx2 = (size_t)(j0 + threadIdx.y + j) * MATN + i0 + threadIdx.x;
        float v = ta[threadIdx.x][threadIdx.y + j];
        __half h = __float2half(v);
        hi[idx2] = h;
        if (wlo) lo[idx2] = __float2half(v - __half2float(h));
    }
}

// per-row residual sumsq of (hS - I); atomicMax into rm (nonneg float-bits). gated.
__global__ void k_rowres(const __half* __restrict__ hS, float* __restrict__ rm,
                         const int* __restrict__ gate) {
    if (gate && *gate == 0) return;
    __shared__ float sm[128];
    int r = blockIdx.x;
    const __half* row = hS + (size_t)r * MATN;
    float acc = 0.f;
    for (int j = threadIdx.x; j < MATN; j += 128) {
        float v = __half2float(row[j]) - ((j == r) ? 1.f : 0.f);
        acc = fmaf(v, v, acc);
    }
    sm[threadIdx.x] = acc; __syncthreads();
    for (int s = 64; s > 0; s >>= 1) {
        if (threadIdx.x < s) sm[threadIdx.x] += sm[threadIdx.x + s];
        __syncthreads();
    }
    if (threadIdx.x == 0) atomicMax((int*)rm, __float_as_int(sm[0]));
}

__global__ void k_det0() { g_f[0] = (g_rmax[0] > TH2) ? 1 : 0; }
__global__ void k_det1() { g_f[1] = (g_f[0] && g_rmax[1] > TH2) ? 1 : 0; }

// copy src->dst when (f0, f1) match (w0, w1)
__global__ void k_copy_sel(const float* __restrict__ src, float* __restrict__ dst,
                           int w0, int w1) {
    if (g_f[0] != w0 || g_f[1] != w1) return;
    for (size_t i = (size_t)blockIdx.x * blockDim.x + threadIdx.x; i < NSQL / 4;
         i += (size_t)gridDim.x * blockDim.x)
        reinterpret_cast<float4*>(dst)[i] = reinterpret_cast<const float4*>(src)[i];
}

// ---------------- driver ----------------
extern "C" void kernel_launch(void* const* d_in, const int* in_sizes, int n_in,
                              void* d_out, int out_size)
{
    const float* H = (const float*)d_in[0];
    float* out = (float*)d_out;

    float *X0, *X1, *S, *P, *v, *y, *part, *scal;
    __half *hA, *lA, *hAT, *hS, *lS, *hP, *lP;
    int* gf;
    float* rmax;
    cudaGetSymbolAddress((void**)&X0, g_X0);   cudaGetSymbolAddress((void**)&X1, g_X1);
    cudaGetSymbolAddress((void**)&S, g_S);     cudaGetSymbolAddress((void**)&P, g_P);
    cudaGetSymbolAddress((void**)&hA, g_hA);   cudaGetSymbolAddress((void**)&lA, g_lA);
    cudaGetSymbolAddress((void**)&hAT, g_hAT);
    cudaGetSymbolAddress((void**)&hS, g_hS);   cudaGetSymbolAddress((void**)&lS, g_lS);
    cudaGetSymbolAddress((void**)&hP, g_hP);   cudaGetSymbolAddress((void**)&lP, g_lP);
    cudaGetSymbolAddress((void**)&v, g_v);     cudaGetSymbolAddress((void**)&y, g_y);
    cudaGetSymbolAddress((void**)&part, g_part); cudaGetSymbolAddress((void**)&scal, g_scal);
    cudaGetSymbolAddress((void**)&gf, g_f);    cudaGetSymbolAddress((void**)&rmax, g_rmax);

    const int* NOG = nullptr;
    k_rst<<<1, 1>>>();

    // --- spectral norm estimate: 10 power iterations, Rayleigh lower bound ---
    k_initv<<<(MATN + 255) / 256, 256>>>(v);
    for (int t = 0; t < 10; ++t) {
        k_sumsq<<<256, 256>>>(v, MATN, part);
        k_finish<<<1, 256>>>(part, scal + 2);
        k_normalize<<<(MATN + 255) / 256, 256>>>(v, scal + 2);
        k_mvn<<<MATN, 128>>>(H, v, y);
        k_mvt<<<MATN / 32, 256>>>(H, y, v);
    }
    k_sumsq<<<256, 256>>>(v, MATN, part);
    k_finish<<<1, 256>>>(part, scal + 2);
    k_normalize<<<(MATN + 255) / 256, 256>>>(v, scal + 2);
    k_mvn<<<MATN, 128>>>(H, v, y);
    k_sumsq<<<256, 256>>>(y, MATN, part);
    k_finish<<<1, 256>>>(part, scal + 1);   // scal[1] = sigma_ray^2

    // --- schedule: L125, 6 x LA, COMP, NS, NS (10 steps) + conditional rescue ---
    const int NSTEP = 10;
    float ca[NSTEP], cb[NSTEP], cc[NSTEP];
    for (int i = 0; i < NSTEP; ++i) {
        if (i == 0)      { ca[i] = 3.115487f;  cb[i] = -5.123742f;   cc[i] = 2.327495f; }
        else if (i <= 6) { ca[i] = 3.894363f;  cb[i] = -10.007316f;  cc[i] = 7.102953f; }
        else if (i == 7) { ca[i] = 2.8426f;    cb[i] = -4.4442f;     cc[i] = 2.6015f; }
        else             { ca[i] = 1.875f;     cb[i] = -1.25f;       cc[i] = 0.375f; }
    }
    const float ANs = 1.875f, BNs = -1.25f, CNs = 0.375f;

    dim3 grd(MATN / 128, MATN / 128);
    dim3 g32(MATN / 32, MATN / 32);
    dim3 b32(32, 8);
    float* Xc = X0;
    float* Xn = X1;

    for (int st = 0; st < NSTEP; ++st) {
        const float a = ca[st], b = cb[st], c = cc[st];
        const bool splitX = (st >= 7);

        k_splitT<<<g32, b32>>>((st == 0) ? H : Xc, hA, lA, hAT, (st == 0) ? 1 : 0, NOG);

        mma_gemm<0, 1><<<grd, 256>>>(hAT, hAT, hAT, hAT, hAT, hAT, 1, S, nullptr,
                                     0, 0, 0, hS, nullptr, NOG);
        k_mirror<<<g32, b32>>>(S, hS, lS, 0, NOG);

        mma_gemm<1, 1><<<grd, 256>>>(hS, hS, hS, hS, hS, hS, 1, P, S, a, b, c,
                                     hP, splitX ? lP : nullptr, NOG);
        k_mirror<<<g32, b32>>>(P, hP, lP, splitX ? 1 : 0, NOG);

        if (splitX)
            mma_gemm<0, 0><<<grd, 256>>>(hA, hP, hA, lP, lA, hP, 3, Xn, nullptr,
                                         0, 0, 0, nullptr, nullptr, NOG);
        else
            mma_gemm<0, 0><<<grd, 256>>>(hA, hP, lA, hP, hA, hP, 2, Xn, nullptr,
                                         0, 0, 0, nullptr, nullptr, NOG);

        float* t = Xc; Xc = Xn; Xn = t;
        if (st == 0) { Xc = X1; Xn = X0; }
    }
    float* Xb = Xc;            // result of step 9
    float* Xrescue = Xn;       // free buffer for conditional NS3 output

    // --- detection 1: S_b = Xb^T Xb (raw), max row-norm of S_b - I ---
    k_splitT<<<g32, b32>>>(Xb, hA, lA, hAT, 0, NOG);
    mma_gemm<0, 1><<<grd, 256>>>(hAT, hAT, hAT, hAT, hAT, hAT, 1, S, nullptr,
                                 0, 0, 0, hS, nullptr, NOG);
    k_mirror<<<g32, b32>>>(S, hS, lS, 0, NOG);
    k_rowres<<<MATN, 128>>>(hS, rmax + 0, NOG);
    k_det0<<<1, 1>>>();

    // --- conditional NS3 (gated on f[0]) ---
    mma_gemm<1, 1><<<grd, 256>>>(hS, hS, hS, hS, hS, hS, 1, P, S, ANs, BNs, CNs,
                                 hP, lP, gf + 0);
    k_mirror<<<g32, b32>>>(P, hP, lP, 1, gf + 0);
    mma_gemm<0, 0><<<grd, 256>>>(hA, hP, hA, lP, lA, hP, 3, Xrescue, nullptr,
                                 0, 0, 0, nullptr, nullptr, gf + 0);

    // --- detection 2 (gated on f[0]) ---
    k_splitT<<<g32, b32>>>(Xrescue, hA, lA, hAT, 0, gf + 0);
    mma_gemm<0, 1><<<grd, 256>>>(hAT, hAT, hAT, hAT, hAT, hAT, 1, S, nullptr,
                                 0, 0, 0, hS, nullptr, gf + 0);
    k_mirror<<<g32, b32>>>(S, hS, lS, 0, gf + 0);
    k_rowres<<<MATN, 128>>>(hS, rmax + 1, gf + 0);
    k_det1<<<1, 1>>>();

    // --- conditional NS4 (gated on f[1]) -> writes out directly ---
    mma_gemm<1, 1><<<grd, 256>>>(hS, hS, hS, hS, hS, hS, 1, P, S, ANs, BNs, CNs,
                                 hP, lP, gf + 1);
    k_mirror<<<g32, b32>>>(P, hP, lP, 1, gf + 1);
    mma_gemm<0, 0><<<grd, 256>>>(hA, hP, hA, lP, lA, hP, 3, out, nullptr,
                                 0, 0, 0, nullptr, nullptr, gf + 1);

    // --- select output for non-NS4 cases ---
    k_copy_sel<<<1024, 256>>>(Xb,      out, 0, 0);   // clean: no rescue fired
    k_copy_sel<<<1024, 256>>>(Xrescue, out, 1, 0);   // NS3 fired, NS4 not
}

// round 16
// speedup vs baseline: 1.1462x; 1.1462x over previous
#include <cuda_runtime.h>
#include <cuda_fp16.h>
#include <cstdint>
#include <math.h>

#define MATN 4096
#define NSQL ((size_t)MATN * (size_t)MATN)

// ---------------- static device scratch ----------------
__device__ float g_S [MATN * MATN];
__device__ __half g_hA [MATN * MATN];
__device__ __half g_lA [MATN * MATN];
__device__ __half g_hB [MATN * MATN];
__device__ __half g_lB [MATN * MATN];
__device__ __half g_hAT[MATN * MATN];
__device__ __half g_hS [MATN * MATN];
__device__ __half g_hP [MATN * MATN];
__device__ __half g_lP [MATN * MATN];
__device__ float g_v[MATN];
__device__ float g_y[MATN];
__device__ float g_part[256];
__device__ float g_scal[4];    // [1]=sigma_ray^2  [2]=tmp norm

// ---------------- helpers ----------------
__device__ __forceinline__ uint32_t smem_u32(const void* p) {
    uint32_t a;
    asm("{ .reg .u64 t; cvta.to.shared.u64 t, %1; cvt.u32.u64 %0, t; }" : "=r"(a) : "l"(p));
    return a;
}
__device__ __forceinline__ void cp16(uint32_t dst, const void* src) {
    asm volatile("cp.async.cg.shared.global [%0], [%1], 16;" :: "r"(dst), "l"(src));
}
#define CP_COMMIT() asm volatile("cp.async.commit_group;" ::: "memory")
#define CP_WAIT(N)  asm volatile("cp.async.wait_group %0;" :: "n"(N) : "memory")

#define LDSM_X4(r, a)                                                           \
    asm volatile("ldmatrix.sync.aligned.m8n8.x4.shared.b16 {%0,%1,%2,%3}, [%4];" \
        : "=r"((r)[0]), "=r"((r)[1]), "=r"((r)[2]), "=r"((r)[3]) : "r"(a))

__device__ __forceinline__ void mma_f16(float* d, const uint32_t* a,
                                        uint32_t b0, uint32_t b1) {
    asm volatile(
        "mma.sync.aligned.m16n8k16.row.col.f32.f16.f16.f32 "
        "{%0,%1,%2,%3}, {%4,%5,%6,%7}, {%8,%9}, {%0,%1,%2,%3};"
        : "+f"(d[0]), "+f"(d[1]), "+f"(d[2]), "+f"(d[3])
        : "r"(a[0]), "r"(a[1]), "r"(a[2]), "r"(a[3]), "r"(b0), "r"(b1));
}

// ---------------- fp16 tensor-core GEMM (mma.sync) ----------------
// D = sum_s A_s * B_s^T ; POLY=1: D = c2*D + c1*E + c0*I.
// TRI=1: only tiles with col-tile >= row-tile.
// Outputs all optional: C (fp32), Hi (half), Lo (half residual vs Hi).
#define BROW 80
#define ABYTES (128 * BROW)
#define BUFBYTES (2 * ABYTES)

template<int POLY, int TRI>
__global__ void __launch_bounds__(256, 2)
mma_gemm(const __half* __restrict__ A0, const __half* __restrict__ B0,
         const __half* __restrict__ A1, const __half* __restrict__ B1,
         const __half* __restrict__ A2, const __half* __restrict__ B2,
         int nseg, float* __restrict__ C, const float* __restrict__ E,
         float c0, float c1, float c2,
         __half* __restrict__ Hi, __half* __restrict__ Lo)
{
    if (TRI && (int)blockIdx.x < (int)blockIdx.y) return;
    __shared__ __align__(16) char smem[2 * BUFBYTES];
    const uint32_t sbase = smem_u32(smem);

    const int tid  = threadIdx.x;
    const int wid  = tid >> 5, lane = tid & 31;
    const int wr   = wid & 3;
    const int wc   = wid >> 2;
    const int row0 = blockIdx.y * 128;
    const int col0 = blockIdx.x * 128;

    const __half* Aseg[3] = {A0, A1, A2};
    const __half* Bseg[3] = {B0, B1, B2};

    float acc[2][8][4];
    #pragma unroll
    for (int i = 0; i < 2; ++i)
        #pragma unroll
        for (int j = 0; j < 8; ++j)
            #pragma unroll
            for (int k = 0; k < 4; ++k) acc[i][j][k] = 0.f;

    auto load_chunk = [&](int ch, int buf) {
        const int seg = ch >> 7, kc = ch & 127;
        const __half* Ap = Aseg[seg] + (size_t)row0 * MATN + kc * 32;
        const __half* Bp = Bseg[seg] + (size_t)col0 * MATN + kc * 32;
        const uint32_t sa = sbase + buf * BUFBYTES;
        const uint32_t sb = sa + ABYTES;
        #pragma unroll
        for (int p = 0; p < 2; ++p) {
            int q = tid + p * 256;
            int r = q >> 2, s = q & 3;
            cp16(sa + r * BROW + s * 16, Ap + (size_t)r * MATN + s * 8);
            cp16(sb + r * BROW + s * 16, Bp + (size_t)r * MATN + s * 8);
        }
        CP_COMMIT();
    };

    const int total = nseg * 128;
    load_chunk(0, 0);

    for (int ch = 0; ch < total; ++ch) {
        const int buf = ch & 1;
        if (ch + 1 < total) { load_chunk(ch + 1, buf ^ 1); CP_WAIT(1); }
        else                { CP_WAIT(0); }
        __syncthreads();

        const uint32_t sa = sbase + buf * BUFBYTES;
        const uint32_t sb = sa + ABYTES;
        #pragma unroll
        for (int kk = 0; kk < 2; ++kk) {
            uint32_t af[2][4], bf[4][4];
            #pragma unroll
            for (int mt = 0; mt < 2; ++mt) {
                uint32_t addr = sa + (uint32_t)(wr * 32 + mt * 16 + (lane & 15)) * BROW
                              + kk * 32 + (lane >> 4) * 16;
                LDSM_X4(af[mt], addr);
            }
            #pragma unroll
            for (int bp = 0; bp < 4; ++bp) {
                int grp = lane >> 3, wi = lane & 7;
                uint32_t addr = sb + (uint32_t)(wc * 64 + bp * 16 + wi + (grp >> 1) * 8) * BROW
                              + kk * 32 + (grp & 1) * 16;
                LDSM_X4(bf[bp], addr);
            }
            #pragma unroll
            for (int mt = 0; mt < 2; ++mt)
                #pragma unroll
                for (int nt = 0; nt < 8; ++nt)
                    mma_f16(acc[mt][nt], af[mt], bf[nt >> 1][(nt & 1) * 2],
                            bf[nt >> 1][(nt & 1) * 2 + 1]);
        }
        __syncthreads();
    }

    #pragma unroll
    for (int mt = 0; mt < 2; ++mt) {
        #pragma unroll
        for (int half = 0; half < 2; ++half) {
            const int rg = row0 + wr * 32 + mt * 16 + (lane >> 2) + half * 8;
            const size_t rowbase = (size_t)rg * MATN;
            #pragma unroll
            for (int nt = 0; nt < 8; ++nt) {
                const int cc = col0 + wc * 64 + nt * 8 + (lane & 3) * 2;
                float v0 = acc[mt][nt][half * 2 + 0];
                float v1 = acc[mt][nt][half * 2 + 1];
                if (POLY) {
                    float2 e = *reinterpret_cast<const float2*>(E + rowbase + cc);
                    v0 = c2 * v0 + c1 * e.x + ((rg == cc)     ? c0 : 0.f);
                    v1 = c2 * v1 + c1 * e.y + ((rg == cc + 1) ? c0 : 0.f);
                }
                if (C) {
                    float2 o = make_float2(v0, v1);
                    *reinterpret_cast<float2*>(C + rowbase + cc) = o;
                }
                if (Hi) {
                    __half2 hh = __floats2half2_rn(v0, v1);
                    *reinterpret_cast<__half2*>(Hi + rowbase + cc) = hh;
                    if (Lo) {
                        float l0 = v0 - __half2float(__low2half(hh));
                        float l1 = v1 - __half2float(__high2half(hh));
                        *reinterpret_cast<__half2*>(Lo + rowbase + cc) =
                            __floats2half2_rn(l0, l1);
                    }
                }
            }
        }
    }
}

// ---------------- small kernels ----------------
__global__ void k_sumsq(const float* __restrict__ x, int n, float* __restrict__ part) {
    __shared__ float sm[256];
    float acc = 0.f;
    for (int i = blockIdx.x * blockDim.x + threadIdx.x; i < n; i += gridDim.x * blockDim.x) {
        float v = x[i]; acc = fmaf(v, v, acc);
    }
    sm[threadIdx.x] = acc; __syncthreads();
    for (int s = 128; s > 0; s >>= 1) {
        if (threadIdx.x < s) sm[threadIdx.x] += sm[threadIdx.x + s];
        __syncthreads();
    }
    if (threadIdx.x == 0) part[blockIdx.x] = sm[0];
}
__global__ void k_finish(const float* __restrict__ part, float* __restrict__ dst) {
    __shared__ float sm[256];
    sm[threadIdx.x] = part[threadIdx.x]; __syncthreads();
    for (int s = 128; s > 0; s >>= 1) {
        if (threadIdx.x < s) sm[threadIdx.x] += sm[threadIdx.x + s];
        __syncthreads();
    }
    if (threadIdx.x == 0) *dst = sm[0];
}
__global__ void k_initv(float* v) {
    int j = blockIdx.x * blockDim.x + threadIdx.x;
    if (j < MATN) {
        unsigned h = (unsigned)j * 2654435761u;
        h ^= h >> 13; h *= 0x5bd1e995u; h ^= h >> 15;
        v[j] = ((float)(h & 0xFFFFu) / 65536.0f) - 0.5f + 0.001f;
    }
}
__global__ void k_normalize(float* v, const float* n2) {
    int j = blockIdx.x * blockDim.x + threadIdx.x;
    float s = rsqrtf(*n2 + 1e-30f);
    if (j < MATN) v[j] *= s;
}
__global__ void k_mvn(const float* __restrict__ H, const float* __restrict__ v,
                      float* __restrict__ y) {
    __shared__ float sm[128];
    int r = blockIdx.x;
    const float* row = H + (size_t)r * MATN;
    float acc = 0.f;
    for (int j = threadIdx.x; j < MATN; j += 128) acc = fmaf(row[j], v[j], acc);
    sm[threadIdx.x] = acc; __syncthreads();
    for (int s = 64; s > 0; s >>= 1) {
        if (threadIdx.x < s) sm[threadIdx.x] += sm[threadIdx.x + s];
        __syncthreads();
    }
    if (threadIdx.x == 0) y[r] = sm[0];
}
// z = (H^T y) * scale  (fixed rescale keeps magnitudes O(1) across iterations)
__global__ void k_mvt(const float* __restrict__ H, const float* __restrict__ y,
                      float* __restrict__ z, float scale) {
    __shared__ float sm[256];
    int tj = threadIdx.x & 31, gi = threadIdx.x >> 5;
    int j = blockIdx.x * 32 + tj;
    float acc = 0.f;
    for (int i = gi * 512; i < gi * 512 + 512; ++i)
        acc = fmaf(H[(size_t)i * MATN + j], y[i], acc);
    sm[threadIdx.x] = acc; __syncthreads();
    if (threadIdx.x < 32) {
        float t = 0.f;
        #pragma unroll
        for (int g = 0; g < 8; ++g) t += sm[threadIdx.x + 32 * g];
        z[j] = t * scale;
    }
}

// step-0 only: split fp32 H (prescaled) -> hi, lo, hiT
__global__ void k_splitT(const float* __restrict__ X,
                         __half* __restrict__ hi, __half* __restrict__ lo,
                         __half* __restrict__ hiT) {
    __shared__ float t[32][33];
    float s = rsqrtf(g_scal[1] + 1e-30f) / 1.10f;
    int x0 = blockIdx.x * 32, y0 = blockIdx.y * 32;
    #pragma unroll
    for (int j = 0; j < 32; j += 8) {
        int r = y0 + threadIdx.y + j, c = x0 + threadIdx.x;
        float v = X[(size_t)r * MATN + c] * s;
        t[threadIdx.y + j][threadIdx.x] = v;
        __half h = __float2half(v);
        hi[(size_t)r * MATN + c] = h;
        lo[(size_t)r * MATN + c] = __float2half(v - __half2float(h));
    }
    __syncthreads();
    #pragma unroll
    for (int j = 0; j < 32; j += 8) {
        int r = x0 + threadIdx.y + j, c = y0 + threadIdx.x;
        hiT[(size_t)r * MATN + c] = __float2half(t[threadIdx.x][threadIdx.y + j]);
    }
}

// half transpose: dst = src^T
__global__ void k_transh(const __half* __restrict__ src, __half* __restrict__ dst) {
    __shared__ __half t[32][33];
    int x0 = blockIdx.x * 32, y0 = blockIdx.y * 32;
    #pragma unroll
    for (int j = 0; j < 32; j += 8)
        t[threadIdx.y + j][threadIdx.x] = src[(size_t)(y0 + threadIdx.y + j) * MATN + x0 + threadIdx.x];
    __syncthreads();
    #pragma unroll
    for (int j = 0; j < 32; j += 8)
        dst[(size_t)(x0 + threadIdx.y + j) * MATN + y0 + threadIdx.x] = t[threadIdx.x][threadIdx.y + j];
}

// mirror half upper -> lower (strictly below diagonal); hi always, lo if wlo
__global__ void k_mirror_h(__half* __restrict__ hi, __half* __restrict__ lo, int wlo) {
    __shared__ __half th[32][33];
    __shared__ __half tl[32][33];
    int bi = blockIdx.y, bj = blockIdx.x;
    if (bj <= bi) return;
    int i0 = bi * 32, j0 = bj * 32;
    #pragma unroll
    for (int j = 0; j < 32; j += 8) {
        size_t idx1 = (size_t)(i0 + threadIdx.y + j) * MATN + j0 + threadIdx.x;
        th[threadIdx.y + j][threadIdx.x] = hi[idx1];
        if (wlo) tl[threadIdx.y + j][threadIdx.x] = lo[idx1];
    }
    __syncthreads();
    #pragma unroll
    for (int j = 0; j < 32; j += 8) {
        size_t idx2 = (size_t)(j0 + threadIdx.y + j) * MATN + i0 + threadIdx.x;
        hi[idx2] = th[threadIdx.x][threadIdx.y + j];
        if (wlo) lo[idx2] = tl[threadIdx.x][threadIdx.y + j];
    }
}

// ---------------- driver ----------------
extern "C" void kernel_launch(void* const* d_in, const int* in_sizes, int n_in,
                              void* d_out, int out_size)
{
    const float* H = (const float*)d_in[0];
    float* out = (float*)d_out;

    float *S, *v, *y, *part, *scal;
    __half *hA, *lA, *hB, *lB, *hAT, *hS, *hP, *lP;
    cudaGetSymbolAddress((void**)&S, g_S);
    cudaGetSymbolAddress((void**)&hA, g_hA);   cudaGetSymbolAddress((void**)&lA, g_lA);
    cudaGetSymbolAddress((void**)&hB, g_hB);   cudaGetSymbolAddress((void**)&lB, g_lB);
    cudaGetSymbolAddress((void**)&hAT, g_hAT);
    cudaGetSymbolAddress((void**)&hS, g_hS);
    cudaGetSymbolAddress((void**)&hP, g_hP);   cudaGetSymbolAddress((void**)&lP, g_lP);
    cudaGetSymbolAddress((void**)&v, g_v);     cudaGetSymbolAddress((void**)&y, g_y);
    cudaGetSymbolAddress((void**)&part, g_part); cudaGetSymbolAddress((void**)&scal, g_scal);

    // --- spectral norm estimate: 10 power iterations, Rayleigh lower bound ---
    // Fixed 1/16384 rescale (sigma_max^2 ~ 4N) keeps iterates O(1); exact
    // normalization only at the end.
    k_initv<<<(MATN + 255) / 256, 256>>>(v);
    for (int t = 0; t < 10; ++t) {
        k_mvn<<<MATN, 128>>>(H, v, y);
        k_mvt<<<MATN / 32, 256>>>(H, y, v, 1.0f / 16384.0f);
    }
    k_sumsq<<<256, 256>>>(v, MATN, part);
    k_finish<<<1, 256>>>(part, scal + 2);
    k_normalize<<<(MATN + 255) / 256, 256>>>(v, scal + 2);
    k_mvn<<<MATN, 128>>>(H, v, y);
    k_sumsq<<<256, 256>>>(y, MATN, part);
    k_finish<<<1, 256>>>(part, scal + 1);   // scal[1] = sigma_ray^2

    // --- schedule: 1 x L125, 7 x LA, 1 x COMP, 2 x NS (11 steps), hardened 0.99 ---
    // All steps: raw S (1 seg), raw P (1 seg).
    // steps 0..7 : X' = (Xh+Xl) * Ph          (2 segs)
    // steps 8..10: X' = Xh*Ph + Xh*Pl + Xl*Ph (3 segs; exact split of computed P)
    const int NSTEP = 11;
    float ca[NSTEP], cb[NSTEP], cc[NSTEP];
    for (int i = 0; i < NSTEP; ++i) {
        if (i == 0)      { ca[i] = 3.115487f;  cb[i] = -5.123742f;   cc[i] = 2.327495f; }
        else if (i <= 7) { ca[i] = 3.894363f;  cb[i] = -10.007316f;  cc[i] = 7.102953f; }
        else if (i == 8) { ca[i] = 2.8426f;    cb[i] = -4.4442f;     cc[i] = 2.6015f; }
        else             { ca[i] = 1.875f;     cb[i] = -1.25f;       cc[i] = 0.375f; }
    }

    dim3 grd(MATN / 128, MATN / 128);   // (32, 32)
    dim3 g32(MATN / 32, MATN / 32);
    dim3 b32(32, 8);

    __half *curh = hA, *curl = lA, *nxth = hB, *nxtl = lB;

    for (int st = 0; st < NSTEP; ++st) {
        const float a = ca[st], b = cb[st], c = cc[st];
        const bool splitX = (st >= 8);
        const bool last   = (st == NSTEP - 1);

        if (st == 0)
            k_splitT<<<g32, b32>>>(H, curh, curl, hAT);   // prescaled split of H
        else
            k_transh<<<g32, b32>>>(curh, hAT);

        // S = Xh^T Xh  (upper tiles): fp32 S (for b-term) + hS
        mma_gemm<0, 1><<<grd, 256>>>(hAT, hAT, hAT, hAT, hAT, hAT, 1, S, nullptr,
                                     0, 0, 0, hS, nullptr);
        k_mirror_h<<<g32, b32>>>(hS, nullptr, 0);

        // P = a I + b S + c Sh^2  (upper tiles; fp32 P never materialized)
        mma_gemm<1, 1><<<grd, 256>>>(hS, hS, hS, hS, hS, hS, 1, nullptr, S, a, b, c,
                                     hP, splitX ? lP : nullptr);
        k_mirror_h<<<g32, b32>>>(hP, lP, splitX ? 1 : 0);

        // X' -> fused split into next half buffers (fp32 only on the last step)
        float* Cout = last ? out : nullptr;
        __half* Hio = last ? nullptr : nxth;
        __half* Loo = last ? nullptr : nxtl;
        if (splitX)
            mma_gemm<0, 0><<<grd, 256>>>(curh, hP, curh, lP, curl, hP, 3, Cout, nullptr,
                                         0, 0, 0, Hio, Loo);
        else
            mma_gemm<0, 0><<<grd, 256>>>(curh, hP, curl, hP, curh, hP, 2, Cout, nullptr,
                                         0, 0, 0, Hio, Loo);

        __half* t;
        t = curh; curh = nxth; nxth = t;
        t = curl; curl = nxtl; nxtl = t;
    }
}

// round 17
// speedup vs baseline: 1.1470x; 1.0007x over previous
#include <cuda_runtime.h>
#include <cuda_fp16.h>
#include <cstdint>
#include <math.h>

#define MATN 4096
#define NSQL ((size_t)MATN * (size_t)MATN)

// ---------------- static device scratch ----------------
__device__ float g_S [MATN * MATN];
__device__ __half g_hA [MATN * MATN];
__device__ __half g_lA [MATN * MATN];
__device__ __half g_hB [MATN * MATN];   // also reused as Hh during power phase
__device__ __half g_lB [MATN * MATN];
__device__ __half g_hAT[MATN * MATN];
__device__ __half g_hS [MATN * MATN];
__device__ __half g_hP [MATN * MATN];
__device__ __half g_lP [MATN * MATN];
__device__ float g_v[MATN];
__device__ float g_y[MATN];
__device__ float g_part[256];
__device__ float g_scal[4];    // [1]=sigma_ray^2  [2]=tmp norm

// ---------------- helpers ----------------
__device__ __forceinline__ uint32_t smem_u32(const void* p) {
    uint32_t a;
    asm("{ .reg .u64 t; cvta.to.shared.u64 t, %1; cvt.u32.u64 %0, t; }" : "=r"(a) : "l"(p));
    return a;
}
__device__ __forceinline__ void cp16(uint32_t dst, const void* src) {
    asm volatile("cp.async.cg.shared.global [%0], [%1], 16;" :: "r"(dst), "l"(src));
}
#define CP_COMMIT() asm volatile("cp.async.commit_group;" ::: "memory")
#define CP_WAIT(N)  asm volatile("cp.async.wait_group %0;" :: "n"(N) : "memory")

#define LDSM_X4(r, a)                                                           \
    asm volatile("ldmatrix.sync.aligned.m8n8.x4.shared.b16 {%0,%1,%2,%3}, [%4];" \
        : "=r"((r)[0]), "=r"((r)[1]), "=r"((r)[2]), "=r"((r)[3]) : "r"(a))

__device__ __forceinline__ void mma_f16(float* d, const uint32_t* a,
                                        uint32_t b0, uint32_t b1) {
    asm volatile(
        "mma.sync.aligned.m16n8k16.row.col.f32.f16.f16.f32 "
        "{%0,%1,%2,%3}, {%4,%5,%6,%7}, {%8,%9}, {%0,%1,%2,%3};"
        : "+f"(d[0]), "+f"(d[1]), "+f"(d[2]), "+f"(d[3])
        : "r"(a[0]), "r"(a[1]), "r"(a[2]), "r"(a[3]), "r"(b0), "r"(b1));
}

// ---------------- fp16 tensor-core GEMM (mma.sync) ----------------
// D = sum_s A_s * B_s^T ; POLY=1: D = c2*D + c1*E + c0*I, E from fp32 (Ef) or half (Eh).
// TRI=1: only tiles with col-tile >= row-tile.
// Outputs all optional: C (fp32), Hi (half), Lo (half residual vs Hi).
#define BROW 80
#define ABYTES (128 * BROW)
#define BUFBYTES (2 * ABYTES)

template<int POLY, int TRI>
__global__ void __launch_bounds__(256, 2)
mma_gemm(const __half* __restrict__ A0, const __half* __restrict__ B0,
         const __half* __restrict__ A1, const __half* __restrict__ B1,
         const __half* __restrict__ A2, const __half* __restrict__ B2,
         int nseg, float* __restrict__ C,
         const float* __restrict__ Ef, const __half* __restrict__ Eh,
         float c0, float c1, float c2,
         __half* __restrict__ Hi, __half* __restrict__ Lo)
{
    if (TRI && (int)blockIdx.x < (int)blockIdx.y) return;
    __shared__ __align__(16) char smem[2 * BUFBYTES];
    const uint32_t sbase = smem_u32(smem);

    const int tid  = threadIdx.x;
    const int wid  = tid >> 5, lane = tid & 31;
    const int wr   = wid & 3;
    const int wc   = wid >> 2;
    const int row0 = blockIdx.y * 128;
    const int col0 = blockIdx.x * 128;

    const __half* Aseg[3] = {A0, A1, A2};
    const __half* Bseg[3] = {B0, B1, B2};

    float acc[2][8][4];
    #pragma unroll
    for (int i = 0; i < 2; ++i)
        #pragma unroll
        for (int j = 0; j < 8; ++j)
            #pragma unroll
            for (int k = 0; k < 4; ++k) acc[i][j][k] = 0.f;

    auto load_chunk = [&](int ch, int buf) {
        const int seg = ch >> 7, kc = ch & 127;
        const __half* Ap = Aseg[seg] + (size_t)row0 * MATN + kc * 32;
        const __half* Bp = Bseg[seg] + (size_t)col0 * MATN + kc * 32;
        const uint32_t sa = sbase + buf * BUFBYTES;
        const uint32_t sb = sa + ABYTES;
        #pragma unroll
        for (int p = 0; p < 2; ++p) {
            int q = tid + p * 256;
            int r = q >> 2, s = q & 3;
            cp16(sa + r * BROW + s * 16, Ap + (size_t)r * MATN + s * 8);
            cp16(sb + r * BROW + s * 16, Bp + (size_t)r * MATN + s * 8);
        }
        CP_COMMIT();
    };

    const int total = nseg * 128;
    load_chunk(0, 0);

    for (int ch = 0; ch < total; ++ch) {
        const int buf = ch & 1;
        if (ch + 1 < total) { load_chunk(ch + 1, buf ^ 1); CP_WAIT(1); }
        else                { CP_WAIT(0); }
        __syncthreads();

        const uint32_t sa = sbase + buf * BUFBYTES;
        const uint32_t sb = sa + ABYTES;
        #pragma unroll
        for (int kk = 0; kk < 2; ++kk) {
            uint32_t af[2][4], bf[4][4];
            #pragma unroll
            for (int mt = 0; mt < 2; ++mt) {
                uint32_t addr = sa + (uint32_t)(wr * 32 + mt * 16 + (lane & 15)) * BROW
                              + kk * 32 + (lane >> 4) * 16;
                LDSM_X4(af[mt], addr);
            }
            #pragma unroll
            for (int bp = 0; bp < 4; ++bp) {
                int grp = lane >> 3, wi = lane & 7;
                uint32_t addr = sb + (uint32_t)(wc * 64 + bp * 16 + wi + (grp >> 1) * 8) * BROW
                              + kk * 32 + (grp & 1) * 16;
                LDSM_X4(bf[bp], addr);
            }
            #pragma unroll
            for (int mt = 0; mt < 2; ++mt)
                #pragma unroll
                for (int nt = 0; nt < 8; ++nt)
                    mma_f16(acc[mt][nt], af[mt], bf[nt >> 1][(nt & 1) * 2],
                            bf[nt >> 1][(nt & 1) * 2 + 1]);
        }
        __syncthreads();
    }

    #pragma unroll
    for (int mt = 0; mt < 2; ++mt) {
        #pragma unroll
        for (int half = 0; half < 2; ++half) {
            const int rg = row0 + wr * 32 + mt * 16 + (lane >> 2) + half * 8;
            const size_t rowbase = (size_t)rg * MATN;
            #pragma unroll
            for (int nt = 0; nt < 8; ++nt) {
                const int cc = col0 + wc * 64 + nt * 8 + (lane & 3) * 2;
                float v0 = acc[mt][nt][half * 2 + 0];
                float v1 = acc[mt][nt][half * 2 + 1];
                if (POLY) {
                    float e0, e1;
                    if (Ef) {
                        float2 e = *reinterpret_cast<const float2*>(Ef + rowbase + cc);
                        e0 = e.x; e1 = e.y;
                    } else {
                        __half2 eh = *reinterpret_cast<const __half2*>(Eh + rowbase + cc);
                        e0 = __half2float(__low2half(eh));
                        e1 = __half2float(__high2half(eh));
                    }
                    v0 = c2 * v0 + c1 * e0 + ((rg == cc)     ? c0 : 0.f);
                    v1 = c2 * v1 + c1 * e1 + ((rg == cc + 1) ? c0 : 0.f);
                }
                if (C) {
                    float2 o = make_float2(v0, v1);
                    *reinterpret_cast<float2*>(C + rowbase + cc) = o;
                }
                if (Hi) {
                    __half2 hh = __floats2half2_rn(v0, v1);
                    *reinterpret_cast<__half2*>(Hi + rowbase + cc) = hh;
                    if (Lo) {
                        float l0 = v0 - __half2float(__low2half(hh));
                        float l1 = v1 - __half2float(__high2half(hh));
                        *reinterpret_cast<__half2*>(Lo + rowbase + cc) =
                            __floats2half2_rn(l0, l1);
                    }
                }
            }
        }
    }
}

// ---------------- small kernels ----------------
__global__ void k_sumsq(const float* __restrict__ x, int n, float* __restrict__ part) {
    __shared__ float sm[256];
    float acc = 0.f;
    for (int i = blockIdx.x * blockDim.x + threadIdx.x; i < n; i += gridDim.x * blockDim.x) {
        float v = x[i]; acc = fmaf(v, v, acc);
    }
    sm[threadIdx.x] = acc; __syncthreads();
    for (int s = 128; s > 0; s >>= 1) {
        if (threadIdx.x < s) sm[threadIdx.x] += sm[threadIdx.x + s];
        __syncthreads();
    }
    if (threadIdx.x == 0) part[blockIdx.x] = sm[0];
}
__global__ void k_finish(const float* __restrict__ part, float* __restrict__ dst) {
    __shared__ float sm[256];
    sm[threadIdx.x] = part[threadIdx.x]; __syncthreads();
    for (int s = 128; s > 0; s >>= 1) {
        if (threadIdx.x < s) sm[threadIdx.x] += sm[threadIdx.x + s];
        __syncthreads();
    }
    if (threadIdx.x == 0) *dst = sm[0];
}
__global__ void k_initv(float* v) {
    int j = blockIdx.x * blockDim.x + threadIdx.x;
    if (j < MATN) {
        unsigned h = (unsigned)j * 2654435761u;
        h ^= h >> 13; h *= 0x5bd1e995u; h ^= h >> 15;
        v[j] = ((float)(h & 0xFFFFu) / 65536.0f) - 0.5f + 0.001f;
    }
}
__global__ void k_normalize(float* v, const float* n2) {
    int j = blockIdx.x * blockDim.x + threadIdx.x;
    float s = rsqrtf(*n2 + 1e-30f);
    if (j < MATN) v[j] *= s;
}
// H (fp32) -> Hh (half), raw
__global__ void k_tohalf(const float* __restrict__ H, __half* __restrict__ Hh) {
    for (size_t i = (size_t)blockIdx.x * blockDim.x + threadIdx.x; i < NSQL / 2;
         i += (size_t)gridDim.x * blockDim.x) {
        float2 v = reinterpret_cast<const float2*>(H)[i];
        reinterpret_cast<__half2*>(Hh)[i] = __floats2half2_rn(v.x, v.y);
    }
}
// y = Hh v  (half matrix, fp32 accumulate)
__global__ void k_mvn_h(const __half* __restrict__ Hh, const float* __restrict__ v,
                        float* __restrict__ y) {
    __shared__ float sm[128];
    int r = blockIdx.x;
    const __half* row = Hh + (size_t)r * MATN;
    float acc = 0.f;
    for (int j = threadIdx.x; j < MATN; j += 128)
        acc = fmaf(__half2float(row[j]), v[j], acc);
    sm[threadIdx.x] = acc; __syncthreads();
    for (int s = 64; s > 0; s >>= 1) {
        if (threadIdx.x < s) sm[threadIdx.x] += sm[threadIdx.x + s];
        __syncthreads();
    }
    if (threadIdx.x == 0) y[r] = sm[0];
}
// z = (Hh^T y) * scale
__global__ void k_mvt_h(const __half* __restrict__ Hh, const float* __restrict__ y,
                        float* __restrict__ z, float scale) {
    __shared__ float sm[256];
    int tj = threadIdx.x & 31, gi = threadIdx.x >> 5;
    int j = blockIdx.x * 32 + tj;
    float acc = 0.f;
    for (int i = gi * 512; i < gi * 512 + 512; ++i)
        acc = fmaf(__half2float(Hh[(size_t)i * MATN + j]), y[i], acc);
    sm[threadIdx.x] = acc; __syncthreads();
    if (threadIdx.x < 32) {
        float t = 0.f;
        #pragma unroll
        for (int g = 0; g < 8; ++g) t += sm[threadIdx.x + 32 * g];
        z[j] = t * scale;
    }
}

// step-0 only: split fp32 H (prescaled) -> hi, lo, hiT
__global__ void k_splitT(const float* __restrict__ X,
                         __half* __restrict__ hi, __half* __restrict__ lo,
                         __half* __restrict__ hiT) {
    __shared__ float t[32][33];
    float s = rsqrtf(g_scal[1] + 1e-30f) / 1.10f;
    int x0 = blockIdx.x * 32, y0 = blockIdx.y * 32;
    #pragma unroll
    for (int j = 0; j < 32; j += 8) {
        int r = y0 + threadIdx.y + j, c = x0 + threadIdx.x;
        float v = X[(size_t)r * MATN + c] * s;
        t[threadIdx.y + j][threadIdx.x] = v;
        __half h = __float2half(v);
        hi[(size_t)r * MATN + c] = h;
        lo[(size_t)r * MATN + c] = __float2half(v - __half2float(h));
    }
    __syncthreads();
    #pragma unroll
    for (int j = 0; j < 32; j += 8) {
        int r = x0 + threadIdx.y + j, c = y0 + threadIdx.x;
        hiT[(size_t)r * MATN + c] = __float2half(t[threadIdx.x][threadIdx.y + j]);
    }
}

// half transpose: dst = src^T
__global__ void k_transh(const __half* __restrict__ src, __half* __restrict__ dst) {
    __shared__ __half t[32][33];
    int x0 = blockIdx.x * 32, y0 = blockIdx.y * 32;
    #pragma unroll
    for (int j = 0; j < 32; j += 8)
        t[threadIdx.y + j][threadIdx.x] = src[(size_t)(y0 + threadIdx.y + j) * MATN + x0 + threadIdx.x];
    __syncthreads();
    #pragma unroll
    for (int j = 0; j < 32; j += 8)
        dst[(size_t)(x0 + threadIdx.y + j) * MATN + y0 + threadIdx.x] = t[threadIdx.x][threadIdx.y + j];
}

// mirror half upper -> lower (strictly below diagonal); hi always, lo if wlo
__global__ void k_mirror_h(__half* __restrict__ hi, __half* __restrict__ lo, int wlo) {
    __shared__ __half th[32][33];
    __shared__ __half tl[32][33];
    int bi = blockIdx.y, bj = blockIdx.x;
    if (bj <= bi) return;
    int i0 = bi * 32, j0 = bj * 32;
    #pragma unroll
    for (int j = 0; j < 32; j += 8) {
        size_t idx1 = (size_t)(i0 + threadIdx.y + j) * MATN + j0 + threadIdx.x;
        th[threadIdx.y + j][threadIdx.x] = hi[idx1];
        if (wlo) tl[threadIdx.y + j][threadIdx.x] = lo[idx1];
    }
    __syncthreads();
    #pragma unroll
    for (int j = 0; j < 32; j += 8) {
        size_t idx2 = (size_t)(j0 + threadIdx.y + j) * MATN + i0 + threadIdx.x;
        hi[idx2] = th[threadIdx.x][threadIdx.y + j];
        if (wlo) lo[idx2] = tl[threadIdx.x][threadIdx.y + j];
    }
}

// ---------------- driver ----------------
extern "C" void kernel_launch(void* const* d_in, const int* in_sizes, int n_in,
                              void* d_out, int out_size)
{
    const float* H = (const float*)d_in[0];
    float* out = (float*)d_out;

    float *S, *v, *y, *part, *scal;
    __half *hA, *lA, *hB, *lB, *hAT, *hS, *hP, *lP;
    cudaGetSymbolAddress((void**)&S, g_S);
    cudaGetSymbolAddress((void**)&hA, g_hA);   cudaGetSymbolAddress((void**)&lA, g_lA);
    cudaGetSymbolAddress((void**)&hB, g_hB);   cudaGetSymbolAddress((void**)&lB, g_lB);
    cudaGetSymbolAddress((void**)&hAT, g_hAT);
    cudaGetSymbolAddress((void**)&hS, g_hS);
    cudaGetSymbolAddress((void**)&hP, g_hP);   cudaGetSymbolAddress((void**)&lP, g_lP);
    cudaGetSymbolAddress((void**)&v, g_v);     cudaGetSymbolAddress((void**)&y, g_y);
    cudaGetSymbolAddress((void**)&part, g_part); cudaGetSymbolAddress((void**)&scal, g_scal);

    // --- spectral norm estimate: 10 power iterations on half(H), Rayleigh bound ---
    // hB is dead until step-0's X' output -> reuse as Hh during this phase.
    k_tohalf<<<2048, 256>>>(H, hB);
    k_initv<<<(MATN + 255) / 256, 256>>>(v);
    for (int t = 0; t < 10; ++t) {
        k_mvn_h<<<MATN, 128>>>(hB, v, y);
        k_mvt_h<<<MATN / 32, 256>>>(hB, y, v, 1.0f / 16384.0f);
    }
    k_sumsq<<<256, 256>>>(v, MATN, part);
    k_finish<<<1, 256>>>(part, scal + 2);
    k_normalize<<<(MATN + 255) / 256, 256>>>(v, scal + 2);
    k_mvn_h<<<MATN, 128>>>(hB, v, y);
    k_sumsq<<<256, 256>>>(y, MATN, part);
    k_finish<<<1, 256>>>(part, scal + 1);   // scal[1] = sigma_ray^2

    // --- schedule: 1 x L125, 7 x LA, 1 x COMP, 2 x NS (11 steps), hardened 0.99 ---
    // All steps: raw S (1 seg), raw P (1 seg).
    // steps 0..7 : X' = (Xh+Xl) * Ph          (2 segs)
    // steps 8..10: X' = Xh*Ph + Xh*Pl + Xl*Ph (3 segs)
    // b-term of P: half hS on steps 0..8 (symmetric, corrected later);
    //              exact fp32 S on steps 9..10.
    const int NSTEP = 11;
    float ca[NSTEP], cb[NSTEP], cc[NSTEP];
    for (int i = 0; i < NSTEP; ++i) {
        if (i == 0)      { ca[i] = 3.115487f;  cb[i] = -5.123742f;   cc[i] = 2.327495f; }
        else if (i <= 7) { ca[i] = 3.894363f;  cb[i] = -10.007316f;  cc[i] = 7.102953f; }
        else if (i == 8) { ca[i] = 2.8426f;    cb[i] = -4.4442f;     cc[i] = 2.6015f; }
        else             { ca[i] = 1.875f;     cb[i] = -1.25f;       cc[i] = 0.375f; }
    }

    dim3 grd(MATN / 128, MATN / 128);   // (32, 32)
    dim3 g32(MATN / 32, MATN / 32);
    dim3 b32(32, 8);

    __half *curh = hA, *curl = lA, *nxth = hB, *nxtl = lB;

    for (int st = 0; st < NSTEP; ++st) {
        const float a = ca[st], b = cb[st], c = cc[st];
        const bool splitX = (st >= 8);
        const bool exactB = (st >= 9);
        const bool last   = (st == NSTEP - 1);

        if (st == 0)
            k_splitT<<<g32, b32>>>(H, curh, curl, hAT);   // prescaled split of H
        else
            k_transh<<<g32, b32>>>(curh, hAT);

        // S = Xh^T Xh (upper tiles): hS always; fp32 S only when b-term needs it
        mma_gemm<0, 1><<<grd, 256>>>(hAT, hAT, hAT, hAT, hAT, hAT, 1,
                                     exactB ? S : nullptr, nullptr, nullptr,
                                     0, 0, 0, hS, nullptr);
        k_mirror_h<<<g32, b32>>>(hS, nullptr, 0);

        // P = a I + b S + c Sh^2  (upper tiles; fp32 P never materialized)
        mma_gemm<1, 1><<<grd, 256>>>(hS, hS, hS, hS, hS, hS, 1, nullptr,
                                     exactB ? S : nullptr, exactB ? nullptr : hS,
                                     a, b, c, hP, splitX ? lP : nullptr);
        k_mirror_h<<<g32, b32>>>(hP, lP, splitX ? 1 : 0);

        // X' -> fused split into next half buffers (fp32 only on the last step)
        float* Cout = last ? out : nullptr;
        __half* Hio = last ? nullptr : nxth;
        __half* Loo = last ? nullptr : nxtl;
        if (splitX)
            mma_gemm<0, 0><<<grd, 256>>>(curh, hP, curh, lP, curl, hP, 3, Cout,
                                         nullptr, nullptr, 0, 0, 0, Hio, Loo);
        else
            mma_gemm<0, 0><<<grd, 256>>>(curh, hP, curl, hP, curh, hP, 2, Cout,
                                         nullptr, nullptr, 0, 0, 0, Hio, Loo);

        __half* t;
        t = curh; curh = nxth; nxth = t;
        t = curl; curl = nxtl; nxtl = t;
    }
}